// round 2
// baseline (speedup 1.0000x reference)
#include <cuda_runtime.h>
#include <math.h>

#define BATCH   4
#define SEQ     2048
#define EMBED   512
#define HIDDEN  2048
#define HEADS   8
#define DHEAD   64
#define M_TOK   (BATCH * SEQ)     // 8192
#define QKV_W3  (3 * EMBED)       // 1536

// ---------------- scratch (device globals; no allocations allowed) ----------
__device__ float g_ln  [M_TOK * EMBED];    // LN output (reused for ln1 & ln2)
__device__ float g_qkv [M_TOK * QKV_W3];   // qkv projection
__device__ float g_att [M_TOK * EMBED];    // attention output (heads concat)
__device__ float g_x1  [M_TOK * EMBED];    // residual after attention
__device__ float g_fc1 [M_TOK * HIDDEN];   // gelu(fc1)

// ---------------- LayerNorm: one warp per row of 512 ------------------------
__global__ void ln_kernel(const float* __restrict__ x,
                          const float* __restrict__ gamma,
                          const float* __restrict__ beta,
                          float* __restrict__ out) {
    int warp = (blockIdx.x * blockDim.x + threadIdx.x) >> 5;
    int lane = threadIdx.x & 31;
    if (warp >= M_TOK) return;

    const float4* xr = (const float4*)(x + (size_t)warp * EMBED);
    float4 v[4];
    float sum = 0.f, sq = 0.f;
#pragma unroll
    for (int i = 0; i < 4; i++) {
        v[i] = xr[lane + 32 * i];
        sum += v[i].x + v[i].y + v[i].z + v[i].w;
        sq  += v[i].x * v[i].x + v[i].y * v[i].y + v[i].z * v[i].z + v[i].w * v[i].w;
    }
#pragma unroll
    for (int o = 16; o; o >>= 1) {
        sum += __shfl_xor_sync(0xffffffffu, sum, o);
        sq  += __shfl_xor_sync(0xffffffffu, sq,  o);
    }
    float mean = sum * (1.f / EMBED);
    float var  = sq * (1.f / EMBED) - mean * mean;
    float rstd = rsqrtf(var + 1e-5f);

    const float4* gg = (const float4*)gamma;
    const float4* bb = (const float4*)beta;
    float4* op = (float4*)(out + (size_t)warp * EMBED);
#pragma unroll
    for (int i = 0; i < 4; i++) {
        float4 gv = gg[lane + 32 * i];
        float4 bv = bb[lane + 32 * i];
        float4 r;
        r.x = (v[i].x - mean) * rstd * gv.x + bv.x;
        r.y = (v[i].y - mean) * rstd * gv.y + bv.y;
        r.z = (v[i].z - mean) * rstd * gv.z + bv.z;
        r.w = (v[i].w - mean) * rstd * gv.w + bv.w;
        op[lane + 32 * i] = r;
    }
}

// ---------------- SGEMM: C = A[M,K] @ B[K,N] + bias (+ epilogue) ------------
// EPI: 1 = bias only, 2 = bias + residual, 3 = bias + exact GELU
__device__ __forceinline__ float gelu_exact(float v) {
    return 0.5f * v * (1.f + erff(v * 0.70710678118654752f));
}

template<int EPI>
__global__ __launch_bounds__(256)
void sgemm_kernel(const float* __restrict__ A, const float* __restrict__ B,
                  const float* __restrict__ bias, const float* __restrict__ res,
                  float* __restrict__ C, int M, int N, int K) {
    __shared__ float As[8][128];
    __shared__ float Bs[8][128];

    int bm = blockIdx.y * 128;
    int bn = blockIdx.x * 128;
    int t  = threadIdx.x;
    int tx = t & 15;          // 0..15 -> columns
    int ty = t >> 4;          // 0..15 -> rows

    float acc[8][8];
#pragma unroll
    for (int i = 0; i < 8; i++)
#pragma unroll
        for (int j = 0; j < 8; j++) acc[i][j] = 0.f;

    int lm = t >> 1;                 // A tile row this thread loads
    int lkq = (t & 1) * 4;           // A tile k-quad
    int lkr = t >> 5;                // B tile k-row
    int lnq = (t & 31) * 4;          // B tile col-quad

    for (int k0 = 0; k0 < K; k0 += 8) {
        float4 av = *(const float4*)(A + (size_t)(bm + lm) * K + k0 + lkq);
        As[lkq + 0][lm] = av.x;
        As[lkq + 1][lm] = av.y;
        As[lkq + 2][lm] = av.z;
        As[lkq + 3][lm] = av.w;
        *(float4*)&Bs[lkr][lnq] =
            *(const float4*)(B + (size_t)(k0 + lkr) * N + bn + lnq);
        __syncthreads();

#pragma unroll
        for (int k = 0; k < 8; k++) {
            float a[8], b[8];
            *(float4*)&a[0] = *(float4*)&As[k][ty * 4];
            *(float4*)&a[4] = *(float4*)&As[k][64 + ty * 4];
            *(float4*)&b[0] = *(float4*)&Bs[k][tx * 4];
            *(float4*)&b[4] = *(float4*)&Bs[k][64 + tx * 4];
#pragma unroll
            for (int i = 0; i < 8; i++)
#pragma unroll
                for (int j = 0; j < 8; j++)
                    acc[i][j] += a[i] * b[j];
        }
        __syncthreads();
    }

#pragma unroll
    for (int i = 0; i < 8; i++) {
        int row = bm + ((i < 4) ? (ty * 4 + i) : (64 + ty * 4 + (i - 4)));
        float* crow = C + (size_t)row * N + bn;
        const float* rrow = (EPI == 2) ? (res + (size_t)row * N + bn) : nullptr;
#pragma unroll
        for (int jh = 0; jh < 2; jh++) {
            int cb = jh ? (64 + tx * 4) : (tx * 4);
            float4 o;
            float vals[4];
#pragma unroll
            for (int jj = 0; jj < 4; jj++) {
                float v = acc[i][jh * 4 + jj] + bias[bn + cb + jj];
                if (EPI == 3) v = gelu_exact(v);
                if (EPI == 2) v += rrow[cb + jj];
                vals[jj] = v;
            }
            o.x = vals[0]; o.y = vals[1]; o.z = vals[2]; o.w = vals[3];
            *(float4*)(crow + cb) = o;
        }
    }
}

// ---------------- Fused flash attention: 1 thread = 1 query -----------------
#define CK 16   // key chunk
__global__ __launch_bounds__(128)
void attn_kernel(const float* __restrict__ qkv, float* __restrict__ o) {
    __shared__ float Ks[CK * 64];
    __shared__ float Vs[CK * 64];

    int bh = blockIdx.y;
    int b  = bh >> 3;
    int h  = bh & 7;
    int t  = threadIdx.x;
    int qi = blockIdx.x * 128 + t;

    const float* qrow = qkv + ((size_t)(b * SEQ + qi)) * QKV_W3 + h * DHEAD;
    float q[64];
    const float4* qp = (const float4*)qrow;
#pragma unroll
    for (int i = 0; i < 16; i++) {
        float4 v = qp[i];
        q[4 * i + 0] = v.x; q[4 * i + 1] = v.y;
        q[4 * i + 2] = v.z; q[4 * i + 3] = v.w;
    }

    float m = -1e30f, l = 0.f;
    float acc[64];
#pragma unroll
    for (int d = 0; d < 64; d++) acc[d] = 0.f;
    const float scale = 0.125f;  // 1/sqrt(64)

    for (int k0 = 0; k0 < SEQ; k0 += CK) {
        // stage K,V chunk: CK*64 floats each = 256 float4 -> 2 per thread each
#pragma unroll
        for (int i = 0; i < 2; i++) {
            int f  = t + 128 * i;        // float4 index within chunk
            int kj = f >> 4;             // key row (16 float4 per row)
            int dq = (f & 15) * 4;
            size_t src = ((size_t)(b * SEQ + k0 + kj)) * QKV_W3 + h * DHEAD + dq;
            *(float4*)&Ks[kj * 64 + dq] = *(const float4*)(qkv + EMBED + src);
            *(float4*)&Vs[kj * 64 + dq] = *(const float4*)(qkv + 2 * EMBED + src);
        }
        __syncthreads();

        float s[CK];
        float cmax = m;
#pragma unroll
        for (int j = 0; j < CK; j++) {
            const float* kr = &Ks[j * 64];
            float s0 = 0.f, s1 = 0.f, s2 = 0.f, s3 = 0.f;
#pragma unroll
            for (int d = 0; d < 64; d += 4) {
                s0 += q[d + 0] * kr[d + 0];
                s1 += q[d + 1] * kr[d + 1];
                s2 += q[d + 2] * kr[d + 2];
                s3 += q[d + 3] * kr[d + 3];
            }
            float sv = ((s0 + s1) + (s2 + s3)) * scale;
            s[j] = sv;
            cmax = fmaxf(cmax, sv);
        }
        float corr = __expf(m - cmax);
        m = cmax;
        l *= corr;
#pragma unroll
        for (int d = 0; d < 64; d++) acc[d] *= corr;
#pragma unroll
        for (int j = 0; j < CK; j++) {
            float p = __expf(s[j] - m);
            l += p;
            const float* vr = &Vs[j * 64];
#pragma unroll
            for (int d = 0; d < 64; d++) acc[d] += p * vr[d];
        }
        __syncthreads();
    }

    float inv = 1.f / l;
    float* op = o + ((size_t)(b * SEQ + qi)) * EMBED + h * DHEAD;
#pragma unroll
    for (int d = 0; d < 64; d += 4) {
        float4 v;
        v.x = acc[d + 0] * inv; v.y = acc[d + 1] * inv;
        v.z = acc[d + 2] * inv; v.w = acc[d + 3] * inv;
        *(float4*)(op + d) = v;
    }
}

// ---------------- driver -----------------------------------------------------
extern "C" void kernel_launch(void* const* d_in, const int* in_sizes, int n_in,
                              void* d_out, int out_size) {
    const float* x      = (const float*)d_in[0];
    const float* ln1_g  = (const float*)d_in[1];
    const float* ln1_b  = (const float*)d_in[2];
    const float* qkv_w  = (const float*)d_in[3];
    const float* qkv_b  = (const float*)d_in[4];
    const float* proj_w = (const float*)d_in[5];
    const float* proj_b = (const float*)d_in[6];
    const float* ln2_g  = (const float*)d_in[7];
    const float* ln2_b  = (const float*)d_in[8];
    const float* fc1_w  = (const float*)d_in[9];
    const float* fc1_b  = (const float*)d_in[10];
    const float* fc2_w  = (const float*)d_in[11];
    const float* fc2_b  = (const float*)d_in[12];
    float* out = (float*)d_out;

    float *p_ln, *p_qkv, *p_att, *p_x1, *p_fc1;
    cudaGetSymbolAddress((void**)&p_ln,  g_ln);
    cudaGetSymbolAddress((void**)&p_qkv, g_qkv);
    cudaGetSymbolAddress((void**)&p_att, g_att);
    cudaGetSymbolAddress((void**)&p_x1,  g_x1);
    cudaGetSymbolAddress((void**)&p_fc1, g_fc1);

    // 1) LN1
    ln_kernel<<<M_TOK / 8, 256>>>(x, ln1_g, ln1_b, p_ln);
    // 2) QKV = LN1 @ qkv_w + qkv_b          [8192,512]x[512,1536]
    sgemm_kernel<1><<<dim3(QKV_W3 / 128, M_TOK / 128), 256>>>(
        p_ln, qkv_w, qkv_b, nullptr, p_qkv, M_TOK, QKV_W3, EMBED);
    // 3) attention
    attn_kernel<<<dim3(SEQ / 128, BATCH * HEADS), 128>>>(p_qkv, p_att);
    // 4) x1 = x + att @ proj_w + proj_b     [8192,512]x[512,512]
    sgemm_kernel<2><<<dim3(EMBED / 128, M_TOK / 128), 256>>>(
        p_att, proj_w, proj_b, x, p_x1, M_TOK, EMBED, EMBED);
    // 5) LN2
    ln_kernel<<<M_TOK / 8, 256>>>(p_x1, ln2_g, ln2_b, p_ln);
    // 6) fc1 = gelu(LN2 @ fc1_w + fc1_b)    [8192,512]x[512,2048]
    sgemm_kernel<3><<<dim3(HIDDEN / 128, M_TOK / 128), 256>>>(
        p_ln, fc1_w, fc1_b, nullptr, p_fc1, M_TOK, HIDDEN, EMBED);
    // 7) out = x1 + fc1 @ fc2_w + fc2_b     [8192,2048]x[2048,512]
    sgemm_kernel<2><<<dim3(EMBED / 128, M_TOK / 128), 256>>>(
        p_fc1, fc2_w, fc2_b, p_x1, out, M_TOK, EMBED, HIDDEN);
}

// round 5
// speedup vs baseline: 1.1468x; 1.1468x over previous
#include <cuda_runtime.h>
#include <math.h>
#include <stdint.h>

#define BATCH   4
#define SEQ     2048
#define EMBED   512
#define HIDDEN  2048
#define HEADS   8
#define DHEAD   64
#define M_TOK   (BATCH * SEQ)     // 8192
#define QKV_W3  (3 * EMBED)       // 1536

// ---------------- scratch (device globals; no allocations allowed) ----------
__device__ float g_ln  [M_TOK * EMBED];
__device__ float g_qkv [M_TOK * QKV_W3];
__device__ float g_att [M_TOK * EMBED];
__device__ float g_x1  [M_TOK * EMBED];
__device__ float g_fc1 [M_TOK * HIDDEN];

// ---------------- LayerNorm: one warp per row of 512 ------------------------
__global__ void ln_kernel(const float* __restrict__ x,
                          const float* __restrict__ gamma,
                          const float* __restrict__ beta,
                          float* __restrict__ out) {
    int warp = (blockIdx.x * blockDim.x + threadIdx.x) >> 5;
    int lane = threadIdx.x & 31;
    if (warp >= M_TOK) return;

    const float4* xr = (const float4*)(x + (size_t)warp * EMBED);
    float4 v[4];
    float sum = 0.f, sq = 0.f;
#pragma unroll
    for (int i = 0; i < 4; i++) {
        v[i] = xr[lane + 32 * i];
        sum += v[i].x + v[i].y + v[i].z + v[i].w;
        sq  += v[i].x * v[i].x + v[i].y * v[i].y + v[i].z * v[i].z + v[i].w * v[i].w;
    }
#pragma unroll
    for (int o = 16; o; o >>= 1) {
        sum += __shfl_xor_sync(0xffffffffu, sum, o);
        sq  += __shfl_xor_sync(0xffffffffu, sq,  o);
    }
    float mean = sum * (1.f / EMBED);
    float var  = sq * (1.f / EMBED) - mean * mean;
    float rstd = rsqrtf(var + 1e-5f);

    const float4* gg = (const float4*)gamma;
    const float4* bb = (const float4*)beta;
    float4* op = (float4*)(out + (size_t)warp * EMBED);
#pragma unroll
    for (int i = 0; i < 4; i++) {
        float4 gv = gg[lane + 32 * i];
        float4 bv = bb[lane + 32 * i];
        float4 r;
        r.x = (v[i].x - mean) * rstd * gv.x + bv.x;
        r.y = (v[i].y - mean) * rstd * gv.y + bv.y;
        r.z = (v[i].z - mean) * rstd * gv.z + bv.z;
        r.w = (v[i].w - mean) * rstd * gv.w + bv.w;
        op[lane + 32 * i] = r;
    }
}

// ---------------- tf32 helpers ----------------------------------------------
__device__ __forceinline__ void split_tf32(float x, uint32_t& hi, uint32_t& lo) {
    asm("cvt.rna.tf32.f32 %0, %1;" : "=r"(hi) : "f"(x));
    float r = x - __uint_as_float(hi);
    asm("cvt.rna.tf32.f32 %0, %1;" : "=r"(lo) : "f"(r));
}

__device__ __forceinline__ void mma_tf32(float* c, const uint32_t* a,
                                         uint32_t b0, uint32_t b1) {
    asm volatile(
        "mma.sync.aligned.m16n8k8.row.col.f32.tf32.tf32.f32 "
        "{%0,%1,%2,%3}, {%4,%5,%6,%7}, {%8,%9}, {%0,%1,%2,%3};"
        : "+f"(c[0]), "+f"(c[1]), "+f"(c[2]), "+f"(c[3])
        : "r"(a[0]), "r"(a[1]), "r"(a[2]), "r"(a[3]), "r"(b0), "r"(b1));
}

__device__ __forceinline__ float gelu_exact(float v) {
    return 0.5f * v * (1.f + erff(v * 0.70710678118654752f));
}

// ---------------- tf32 3x-split tensor-core GEMM -----------------------------
// C[M,N] = A[M,K] @ B[K,N] + bias, EPI: 1=bias, 2=bias+res, 3=bias+GELU
// Block: 128x128 tile, BK=16, 256 threads, 8 warps (4M x 2N), warp tile 32x64.
#define SA 132   // padded smem row stride (floats)

template<int EPI>
__global__ __launch_bounds__(256)
void tgemm_kernel(const float* __restrict__ A, const float* __restrict__ B,
                  const float* __restrict__ bias, const float* __restrict__ res,
                  float* __restrict__ C, int M, int N, int K) {
    __shared__ __align__(16) float As[2][16][SA];   // [k][m]
    __shared__ __align__(16) float Bs[2][16][SA];   // [k][n]

    const int t    = threadIdx.x;
    const int bm   = blockIdx.y * 128;
    const int bn   = blockIdx.x * 128;
    const int w    = t >> 5;
    const int lane = t & 31;
    const int wm   = (w & 3) * 32;     // warp M origin in tile
    const int wn   = (w >> 2) * 64;    // warp N origin in tile
    const int g    = lane >> 2;        // group id 0..7
    const int c    = lane & 3;         // thread-in-group 0..3

    float acc[2][8][4];
#pragma unroll
    for (int i = 0; i < 2; i++)
#pragma unroll
        for (int j = 0; j < 8; j++)
#pragma unroll
            for (int q = 0; q < 4; q++) acc[i][j][q] = 0.f;

    // global load pointers: each thread loads 8 contiguous floats of A and of B
    const int a_row = t >> 1;
    const int a_col = 8 * (t & 1);
    const int b_row = t >> 4;
    const int b_col = 8 * (t & 15);
    const float* aptr = A + (size_t)(bm + a_row) * K + a_col;
    const float* bptr = B + (size_t)b_row * N + bn + b_col;

    const int nk = K >> 4;

    // prefetch tile 0
    float4 av0 = *(const float4*)(aptr);
    float4 av1 = *(const float4*)(aptr + 4);
    float4 bv0 = *(const float4*)(bptr);
    float4 bv1 = *(const float4*)(bptr + 4);

    // store tile 0 -> buf 0
    {
        float av[8] = {av0.x, av0.y, av0.z, av0.w, av1.x, av1.y, av1.z, av1.w};
#pragma unroll
        for (int q = 0; q < 8; q++) As[0][a_col + q][a_row] = av[q];
        *(float4*)&Bs[0][b_row][b_col]     = bv0;
        *(float4*)&Bs[0][b_row][b_col + 4] = bv1;
    }
    __syncthreads();

    for (int kt = 0; kt < nk; kt++) {
        const int buf = kt & 1;
        const bool more = (kt + 1 < nk);
        if (more) {
            const float* ap = aptr + (kt + 1) * 16;
            const float* bp = bptr + (size_t)(kt + 1) * 16 * N;
            av0 = *(const float4*)(ap);
            av1 = *(const float4*)(ap + 4);
            bv0 = *(const float4*)(bp);
            bv1 = *(const float4*)(bp + 4);
        }

#pragma unroll
        for (int ks = 0; ks < 2; ks++) {
            const int k8 = ks * 8;
            uint32_t bhi[8][2], blo[8][2];
#pragma unroll
            for (int j = 0; j < 8; j++) {
                float b0 = Bs[buf][k8 + c][wn + 8 * j + g];
                float b1 = Bs[buf][k8 + c + 4][wn + 8 * j + g];
                split_tf32(b0, bhi[j][0], blo[j][0]);
                split_tf32(b1, bhi[j][1], blo[j][1]);
            }
#pragma unroll
            for (int i = 0; i < 2; i++) {
                const int m0 = wm + 16 * i;
                uint32_t ahi[4], alo[4];
                float a0 = As[buf][k8 + c][m0 + g];
                float a1 = As[buf][k8 + c][m0 + g + 8];
                float a2 = As[buf][k8 + c + 4][m0 + g];
                float a3 = As[buf][k8 + c + 4][m0 + g + 8];
                split_tf32(a0, ahi[0], alo[0]);
                split_tf32(a1, ahi[1], alo[1]);
                split_tf32(a2, ahi[2], alo[2]);
                split_tf32(a3, ahi[3], alo[3]);
#pragma unroll
                for (int j = 0; j < 8; j++) {
                    mma_tf32(acc[i][j], alo, bhi[j][0], bhi[j][1]);
                    mma_tf32(acc[i][j], ahi, blo[j][0], blo[j][1]);
                    mma_tf32(acc[i][j], ahi, bhi[j][0], bhi[j][1]);
                }
            }
        }

        if (more) {
            float av[8] = {av0.x, av0.y, av0.z, av0.w, av1.x, av1.y, av1.z, av1.w};
#pragma unroll
            for (int q = 0; q < 8; q++) As[buf ^ 1][a_col + q][a_row] = av[q];
            *(float4*)&Bs[buf ^ 1][b_row][b_col]     = bv0;
            *(float4*)&Bs[buf ^ 1][b_row][b_col + 4] = bv1;
        }
        __syncthreads();
    }

    // epilogue: c0=(r,n) c1=(r,n+1) c2=(r+8,n) c3=(r+8,n+1), n = wn+8j+2c
#pragma unroll
    for (int i = 0; i < 2; i++) {
        const int r0 = bm + wm + 16 * i + g;
#pragma unroll
        for (int j = 0; j < 8; j++) {
            const int n = bn + wn + 8 * j + 2 * c;
            float bx = bias[n], by = bias[n + 1];
#pragma unroll
            for (int half = 0; half < 2; half++) {
                const int row = r0 + 8 * half;
                float v0 = acc[i][j][2 * half + 0] + bx;
                float v1 = acc[i][j][2 * half + 1] + by;
                if (EPI == 3) { v0 = gelu_exact(v0); v1 = gelu_exact(v1); }
                if (EPI == 2) {
                    const float2 rv = *(const float2*)(res + (size_t)row * N + n);
                    v0 += rv.x; v1 += rv.y;
                }
                float2 o; o.x = v0; o.y = v1;
                *(float2*)(C + (size_t)row * N + n) = o;
            }
        }
    }
}

// ---------------- Fused flash attention: 1 thread = 1 query -----------------
#define CK 16   // key chunk
__global__ __launch_bounds__(128)
void attn_kernel(const float* __restrict__ qkv, float* __restrict__ o) {
    __shared__ float Ks[CK * 64];
    __shared__ float Vs[CK * 64];

    int bh = blockIdx.y;
    int b  = bh >> 3;
    int h  = bh & 7;
    int t  = threadIdx.x;
    int qi = blockIdx.x * 128 + t;

    const float* qrow = qkv + ((size_t)(b * SEQ + qi)) * QKV_W3 + h * DHEAD;
    float q[64];
    const float4* qp = (const float4*)qrow;
#pragma unroll
    for (int i = 0; i < 16; i++) {
        float4 v = qp[i];
        q[4 * i + 0] = v.x; q[4 * i + 1] = v.y;
        q[4 * i + 2] = v.z; q[4 * i + 3] = v.w;
    }

    float m = -1e30f, l = 0.f;
    float acc[64];
#pragma unroll
    for (int d = 0; d < 64; d++) acc[d] = 0.f;
    const float scale = 0.125f;

    for (int k0 = 0; k0 < SEQ; k0 += CK) {
#pragma unroll
        for (int i = 0; i < 2; i++) {
            int f  = t + 128 * i;
            int kj = f >> 4;
            int dq = (f & 15) * 4;
            size_t src = ((size_t)(b * SEQ + k0 + kj)) * QKV_W3 + h * DHEAD + dq;
            *(float4*)&Ks[kj * 64 + dq] = *(const float4*)(qkv + EMBED + src);
            *(float4*)&Vs[kj * 64 + dq] = *(const float4*)(qkv + 2 * EMBED + src);
        }
        __syncthreads();

        float s[CK];
        float cmax = m;
#pragma unroll
        for (int j = 0; j < CK; j++) {
            const float* kr = &Ks[j * 64];
            float s0 = 0.f, s1 = 0.f, s2 = 0.f, s3 = 0.f;
#pragma unroll
            for (int d = 0; d < 64; d += 4) {
                s0 += q[d + 0] * kr[d + 0];
                s1 += q[d + 1] * kr[d + 1];
                s2 += q[d + 2] * kr[d + 2];
                s3 += q[d + 3] * kr[d + 3];
            }
            float sv = ((s0 + s1) + (s2 + s3)) * scale;
            s[j] = sv;
            cmax = fmaxf(cmax, sv);
        }
        float corr = __expf(m - cmax);
        m = cmax;
        l *= corr;
#pragma unroll
        for (int d = 0; d < 64; d++) acc[d] *= corr;
#pragma unroll
        for (int j = 0; j < CK; j++) {
            float p = __expf(s[j] - m);
            l += p;
            const float* vr = &Vs[j * 64];
#pragma unroll
            for (int d = 0; d < 64; d++) acc[d] += p * vr[d];
        }
        __syncthreads();
    }

    float inv = 1.f / l;
    float* op = o + ((size_t)(b * SEQ + qi)) * EMBED + h * DHEAD;
#pragma unroll
    for (int d = 0; d < 64; d += 4) {
        float4 v;
        v.x = acc[d + 0] * inv; v.y = acc[d + 1] * inv;
        v.z = acc[d + 2] * inv; v.w = acc[d + 3] * inv;
        *(float4*)(op + d) = v;
    }
}

// ---------------- driver -----------------------------------------------------
extern "C" void kernel_launch(void* const* d_in, const int* in_sizes, int n_in,
                              void* d_out, int out_size) {
    const float* x      = (const float*)d_in[0];
    const float* ln1_g  = (const float*)d_in[1];
    const float* ln1_b  = (const float*)d_in[2];
    const float* qkv_w  = (const float*)d_in[3];
    const float* qkv_b  = (const float*)d_in[4];
    const float* proj_w = (const float*)d_in[5];
    const float* proj_b = (const float*)d_in[6];
    const float* ln2_g  = (const float*)d_in[7];
    const float* ln2_b  = (const float*)d_in[8];
    const float* fc1_w  = (const float*)d_in[9];
    const float* fc1_b  = (const float*)d_in[10];
    const float* fc2_w  = (const float*)d_in[11];
    const float* fc2_b  = (const float*)d_in[12];
    float* out = (float*)d_out;

    float *p_ln, *p_qkv, *p_att, *p_x1, *p_fc1;
    cudaGetSymbolAddress((void**)&p_ln,  g_ln);
    cudaGetSymbolAddress((void**)&p_qkv, g_qkv);
    cudaGetSymbolAddress((void**)&p_att, g_att);
    cudaGetSymbolAddress((void**)&p_x1,  g_x1);
    cudaGetSymbolAddress((void**)&p_fc1, g_fc1);

    // 1) LN1
    ln_kernel<<<M_TOK / 8, 256>>>(x, ln1_g, ln1_b, p_ln);
    // 2) QKV = LN1 @ qkv_w + qkv_b          [8192,512]x[512,1536]
    tgemm_kernel<1><<<dim3(QKV_W3 / 128, M_TOK / 128), 256>>>(
        p_ln, qkv_w, qkv_b, nullptr, p_qkv, M_TOK, QKV_W3, EMBED);
    // 3) attention
    attn_kernel<<<dim3(SEQ / 128, BATCH * HEADS), 128>>>(p_qkv, p_att);
    // 4) x1 = x + att @ proj_w + proj_b     [8192,512]x[512,512]
    tgemm_kernel<2><<<dim3(EMBED / 128, M_TOK / 128), 256>>>(
        p_att, proj_w, proj_b, x, p_x1, M_TOK, EMBED, EMBED);
    // 5) LN2
    ln_kernel<<<M_TOK / 8, 256>>>(p_x1, ln2_g, ln2_b, p_ln);
    // 6) fc1 = gelu(LN2 @ fc1_w + fc1_b)    [8192,512]x[512,2048]
    tgemm_kernel<3><<<dim3(HIDDEN / 128, M_TOK / 128), 256>>>(
        p_ln, fc1_w, fc1_b, nullptr, p_fc1, M_TOK, HIDDEN, EMBED);
    // 7) out = x1 + fc1 @ fc2_w + fc2_b     [8192,2048]x[2048,512]
    tgemm_kernel<2><<<dim3(EMBED / 128, M_TOK / 128), 256>>>(
        p_fc1, fc2_w, fc2_b, p_x1, out, M_TOK, EMBED, HIDDEN);
}

// round 8
// speedup vs baseline: 3.1470x; 2.7441x over previous
#include <cuda_runtime.h>
#include <cuda_bf16.h>
#include <math.h>
#include <stdint.h>

#define BATCH   4
#define SEQ     2048
#define EMBED   512
#define HIDDEN  2048
#define HEADS   8
#define DHEAD   64
#define M_TOK   (BATCH * SEQ)     // 8192
#define QKV_W3  (3 * EMBED)       // 1536
#define NBH     (BATCH * HEADS)   // 32

// ---------------- scratch (device globals; no allocations allowed) ----------
__device__ float g_ln  [M_TOK * EMBED];
__device__ float g_qkv [M_TOK * QKV_W3];
__device__ float g_att [M_TOK * EMBED];
__device__ float g_x1  [M_TOK * EMBED];
__device__ float g_fc1 [M_TOK * HIDDEN];
// packed bf16x2 (hi/lo split) operands for attention
__device__ uint32_t g_qh[NBH * 32 * SEQ];   // [bh][d2][q]
__device__ uint32_t g_ql[NBH * 32 * SEQ];
__device__ uint32_t g_kh[NBH * 32 * SEQ];   // [bh][d2][k]
__device__ uint32_t g_kl[NBH * 32 * SEQ];
__device__ uint32_t g_vh[NBH * 1024 * 64];  // [bh][kp][d]
__device__ uint32_t g_vl[NBH * 1024 * 64];

// ---------------- helpers ----------------------------------------------------
__device__ __forceinline__ void split2(float x0, float x1, uint32_t& hi, uint32_t& lo) {
    __nv_bfloat16 h0 = __float2bfloat16(x0);
    __nv_bfloat16 h1 = __float2bfloat16(x1);
    float r0 = x0 - __bfloat162float(h0);
    float r1 = x1 - __bfloat162float(h1);
    __nv_bfloat162 hp; hp.x = h0; hp.y = h1;
    __nv_bfloat162 lp; lp.x = __float2bfloat16(r0); lp.y = __float2bfloat16(r1);
    hi = *reinterpret_cast<uint32_t*>(&hp);
    lo = *reinterpret_cast<uint32_t*>(&lp);
}

__device__ __forceinline__ void mma_bf16(float* c, const uint32_t* a,
                                         uint32_t b0, uint32_t b1) {
    asm volatile(
        "mma.sync.aligned.m16n8k16.row.col.f32.bf16.bf16.f32 "
        "{%0,%1,%2,%3}, {%4,%5,%6,%7}, {%8,%9}, {%0,%1,%2,%3};"
        : "+f"(c[0]), "+f"(c[1]), "+f"(c[2]), "+f"(c[3])
        : "r"(a[0]), "r"(a[1]), "r"(a[2]), "r"(a[3]), "r"(b0), "r"(b1));
}

__device__ __forceinline__ float gelu_exact(float v) {
    return 0.5f * v * (1.f + erff(v * 0.70710678118654752f));
}

// ---------------- LayerNorm: one warp per row of 512 ------------------------
__global__ void ln_kernel(const float* __restrict__ x,
                          const float* __restrict__ gamma,
                          const float* __restrict__ beta,
                          float* __restrict__ out) {
    int warp = (blockIdx.x * blockDim.x + threadIdx.x) >> 5;
    int lane = threadIdx.x & 31;
    if (warp >= M_TOK) return;
    const float4* xr = (const float4*)(x + (size_t)warp * EMBED);
    float4 v[4];
    float sum = 0.f, sq = 0.f;
#pragma unroll
    for (int i = 0; i < 4; i++) {
        v[i] = xr[lane + 32 * i];
        sum += v[i].x + v[i].y + v[i].z + v[i].w;
        sq  += v[i].x * v[i].x + v[i].y * v[i].y + v[i].z * v[i].z + v[i].w * v[i].w;
    }
#pragma unroll
    for (int o = 16; o; o >>= 1) {
        sum += __shfl_xor_sync(0xffffffffu, sum, o);
        sq  += __shfl_xor_sync(0xffffffffu, sq,  o);
    }
    float mean = sum * (1.f / EMBED);
    float var  = sq * (1.f / EMBED) - mean * mean;
    float rstd = rsqrtf(var + 1e-5f);
    const float4* gg = (const float4*)gamma;
    const float4* bb = (const float4*)beta;
    float4* op = (float4*)(out + (size_t)warp * EMBED);
#pragma unroll
    for (int i = 0; i < 4; i++) {
        float4 gv = gg[lane + 32 * i];
        float4 bv = bb[lane + 32 * i];
        float4 r;
        r.x = (v[i].x - mean) * rstd * gv.x + bv.x;
        r.y = (v[i].y - mean) * rstd * gv.y + bv.y;
        r.z = (v[i].z - mean) * rstd * gv.z + bv.z;
        r.w = (v[i].w - mean) * rstd * gv.w + bv.w;
        op[lane + 32 * i] = r;
    }
}

// ---------------- bf16 3x-split tensor-core GEMM -----------------------------
// C[M,N] = A[M,K] @ B[K,N] + bias; EPI: 1=bias, 2=bias+res, 3=bias+GELU
// 128x128 tile, BK=16, 256 thr, 8 warps (4M x 2N), warp tile 32x64.
// smem holds pre-split bf16x2 pairs along k: [k2][m] / [k2][n], stride 136.
#define GST 136

template<int EPI>
__global__ __launch_bounds__(256)
void bgemm_kernel(const float* __restrict__ A, const float* __restrict__ B,
                  const float* __restrict__ bias, const float* __restrict__ res,
                  float* __restrict__ C, int M, int N, int K) {
    __shared__ __align__(16) uint32_t Ah[2][8][GST], Al[2][8][GST];
    __shared__ __align__(16) uint32_t Bh[2][8][GST], Bl[2][8][GST];

    const int t    = threadIdx.x;
    const int bm   = blockIdx.y * 128;
    const int bn   = blockIdx.x * 128;
    const int w    = t >> 5;
    const int lane = t & 31;
    const int wm   = (w & 3) * 32;
    const int wn   = (w >> 2) * 64;
    const int g    = lane >> 2;
    const int c    = lane & 3;

    float acc[2][8][4];
#pragma unroll
    for (int i = 0; i < 2; i++)
#pragma unroll
        for (int j = 0; j < 8; j++)
#pragma unroll
            for (int q = 0; q < 4; q++) acc[i][j][q] = 0.f;

    const int a_row = t >> 1;
    const int a_k8  = 8 * (t & 1);
    const int b_kp  = t >> 5;
    const int b_n4  = (t & 31) * 4;
    const float* aptr = A + (size_t)(bm + a_row) * K + a_k8;
    const float* bptr = B + (size_t)(2 * b_kp) * N + bn + b_n4;
    const int nk = K >> 4;

    float4 av0 = *(const float4*)(aptr);
    float4 av1 = *(const float4*)(aptr + 4);
    float4 bv0 = *(const float4*)(bptr);
    float4 bv1 = *(const float4*)(bptr + N);

    // stage tile 0 -> buf 0
    {
        float af[8] = {av0.x, av0.y, av0.z, av0.w, av1.x, av1.y, av1.z, av1.w};
#pragma unroll
        for (int q = 0; q < 4; q++) {
            uint32_t hi, lo;
            split2(af[2 * q], af[2 * q + 1], hi, lo);
            Ah[0][a_k8 / 2 + q][a_row] = hi;
            Al[0][a_k8 / 2 + q][a_row] = lo;
        }
        float r0[4] = {bv0.x, bv0.y, bv0.z, bv0.w};
        float r1[4] = {bv1.x, bv1.y, bv1.z, bv1.w};
        uint32_t hi[4], lo[4];
#pragma unroll
        for (int e = 0; e < 4; e++) split2(r0[e], r1[e], hi[e], lo[e]);
        *(uint4*)&Bh[0][b_kp][b_n4] = *(uint4*)hi;
        *(uint4*)&Bl[0][b_kp][b_n4] = *(uint4*)lo;
    }
    __syncthreads();

    for (int kt = 0; kt < nk; kt++) {
        const int buf = kt & 1;
        const bool more = (kt + 1 < nk);
        if (more) {
            const float* ap = aptr + (kt + 1) * 16;
            const float* bp = bptr + (size_t)(kt + 1) * 16 * N;
            av0 = *(const float4*)(ap);
            av1 = *(const float4*)(ap + 4);
            bv0 = *(const float4*)(bp);
            bv1 = *(const float4*)(bp + N);
        }

        // load A fragments for both i-tiles
        uint32_t ah[2][4], al[2][4];
#pragma unroll
        for (int i = 0; i < 2; i++) {
            const int m0 = wm + 16 * i;
            ah[i][0] = Ah[buf][c][m0 + g];     ah[i][1] = Ah[buf][c][m0 + g + 8];
            ah[i][2] = Ah[buf][c + 4][m0 + g]; ah[i][3] = Ah[buf][c + 4][m0 + g + 8];
            al[i][0] = Al[buf][c][m0 + g];     al[i][1] = Al[buf][c][m0 + g + 8];
            al[i][2] = Al[buf][c + 4][m0 + g]; al[i][3] = Al[buf][c + 4][m0 + g + 8];
        }
#pragma unroll
        for (int j = 0; j < 8; j++) {
            const int n = wn + 8 * j + g;
            uint32_t b0h = Bh[buf][c][n],     b1h = Bh[buf][c + 4][n];
            uint32_t b0l = Bl[buf][c][n],     b1l = Bl[buf][c + 4][n];
#pragma unroll
            for (int i = 0; i < 2; i++) {
                mma_bf16(acc[i][j], al[i], b0h, b1h);
                mma_bf16(acc[i][j], ah[i], b0l, b1l);
                mma_bf16(acc[i][j], ah[i], b0h, b1h);
            }
        }

        if (more) {
            float af[8] = {av0.x, av0.y, av0.z, av0.w, av1.x, av1.y, av1.z, av1.w};
#pragma unroll
            for (int q = 0; q < 4; q++) {
                uint32_t hi, lo;
                split2(af[2 * q], af[2 * q + 1], hi, lo);
                Ah[buf ^ 1][a_k8 / 2 + q][a_row] = hi;
                Al[buf ^ 1][a_k8 / 2 + q][a_row] = lo;
            }
            float r0[4] = {bv0.x, bv0.y, bv0.z, bv0.w};
            float r1[4] = {bv1.x, bv1.y, bv1.z, bv1.w};
            uint32_t hi[4], lo[4];
#pragma unroll
            for (int e = 0; e < 4; e++) split2(r0[e], r1[e], hi[e], lo[e]);
            *(uint4*)&Bh[buf ^ 1][b_kp][b_n4] = *(uint4*)hi;
            *(uint4*)&Bl[buf ^ 1][b_kp][b_n4] = *(uint4*)lo;
        }
        __syncthreads();
    }

    // epilogue (C-frag: c0=(g,2c) c1=(g,2c+1) c2=(g+8,2c) c3=(g+8,2c+1))
#pragma unroll
    for (int i = 0; i < 2; i++) {
        const int r0 = bm + wm + 16 * i + g;
#pragma unroll
        for (int j = 0; j < 8; j++) {
            const int n = bn + wn + 8 * j + 2 * c;
            float bx = bias[n], by = bias[n + 1];
#pragma unroll
            for (int half = 0; half < 2; half++) {
                const int row = r0 + 8 * half;
                float v0 = acc[i][j][2 * half + 0] + bx;
                float v1 = acc[i][j][2 * half + 1] + by;
                if (EPI == 3) { v0 = gelu_exact(v0); v1 = gelu_exact(v1); }
                if (EPI == 2) {
                    const float2 rv = *(const float2*)(res + (size_t)row * N + n);
                    v0 += rv.x; v1 += rv.y;
                }
                float2 o; o.x = v0; o.y = v1;
                *(float2*)(C + (size_t)row * N + n) = o;
            }
        }
    }
}

// ---------------- pre-convert: qkv fp32 -> packed bf16x2 hi/lo ---------------
// grid (16 token-chunks, 32 bh), 256 threads. Q,K transposed to [d2][tok];
// V packed over key-pairs [kp][d].
__global__ __launch_bounds__(256)
void pconv_kernel(const float* __restrict__ qkv,
                  uint32_t* __restrict__ qh, uint32_t* __restrict__ ql,
                  uint32_t* __restrict__ kh, uint32_t* __restrict__ kl,
                  uint32_t* __restrict__ vh, uint32_t* __restrict__ vl) {
    __shared__ float S[64][133];
    const int t  = threadIdx.x;
    const int ck = blockIdx.x;
    const int bh = blockIdx.y;
    const int b  = bh >> 3;
    const int h  = bh & 7;
    const int s0 = ck * 128;
    const float* base = qkv + ((size_t)(b * SEQ + s0)) * QKV_W3 + h * DHEAD;

#pragma unroll
    for (int part = 0; part < 2; part++) {  // 0 = Q, 1 = K
        const float* src = base + part * EMBED;
        uint32_t* oh = part ? kh : qh;
        uint32_t* ol = part ? kl : ql;
        __syncthreads();
#pragma unroll
        for (int r = 0; r < 8; r++) {
            int fi  = t + 256 * r;
            int tok = fi >> 4;
            int dq  = (fi & 15) * 4;
            float4 v = *(const float4*)(src + (size_t)tok * QKV_W3 + dq);
            S[dq + 0][tok] = v.x; S[dq + 1][tok] = v.y;
            S[dq + 2][tok] = v.z; S[dq + 3][tok] = v.w;
        }
        __syncthreads();
#pragma unroll
        for (int r = 0; r < 16; r++) {
            int oi = t + 256 * r;
            int d2 = oi >> 7;
            int q  = oi & 127;
            uint32_t hi, lo;
            split2(S[2 * d2][q], S[2 * d2 + 1][q], hi, lo);
            size_t off = ((size_t)bh * 32 + d2) * SEQ + s0 + q;
            oh[off] = hi; ol[off] = lo;
        }
    }
    // V: direct (pairs of adjacent keys at fixed d)
#pragma unroll
    for (int r = 0; r < 4; r++) {
        int oi = t + 256 * r;           // 1024 uint4 total
        int kp = oi >> 4;
        int d4 = (oi & 15) * 4;
        const float* vb = base + 2 * EMBED + (size_t)(2 * kp) * QKV_W3 + d4;
        float4 a0 = *(const float4*)vb;
        float4 a1 = *(const float4*)(vb + QKV_W3);
        float e0[4] = {a0.x, a0.y, a0.z, a0.w};
        float e1[4] = {a1.x, a1.y, a1.z, a1.w};
        uint32_t hi[4], lo[4];
#pragma unroll
        for (int e = 0; e < 4; e++) split2(e0[e], e1[e], hi[e], lo[e]);
        size_t off = ((size_t)bh * 1024 + ck * 64 + kp) * 64 + d4;
        *(uint4*)&vh[off] = *(uint4*)hi;
        *(uint4*)&vl[off] = *(uint4*)lo;
    }
}

// ---------------- tensor-core flash attention --------------------------------
// block = (128 q) x (b,h); 8 warps x 16 q-rows each; K-chunk 128, bf16 3-split.
#define AQH 0
#define AQL 4352
#define AKH 8704
#define AKL 13056
#define AVH 17408
#define AVL 22016
#define ASM_U32 26624
#define ASM_BYTES (ASM_U32 * 4)

__global__ __launch_bounds__(256, 1)
void attn2_kernel(const uint32_t* __restrict__ qh, const uint32_t* __restrict__ ql,
                  const uint32_t* __restrict__ kh, const uint32_t* __restrict__ kl,
                  const uint32_t* __restrict__ vh, const uint32_t* __restrict__ vl,
                  float* __restrict__ o) {
    extern __shared__ __align__(16) uint32_t sm[];
    uint32_t* QH = sm + AQH; uint32_t* QL = sm + AQL;
    uint32_t* KH = sm + AKH; uint32_t* KL = sm + AKL;
    uint32_t* VH = sm + AVH; uint32_t* VL = sm + AVL;

    const int t    = threadIdx.x;
    const int w    = t >> 5;
    const int lane = t & 31;
    const int g    = lane >> 2;
    const int c    = lane & 3;
    const int bh   = blockIdx.y;
    const int b    = bh >> 3;
    const int h    = bh & 7;
    const int q0g  = blockIdx.x * 128;
    const int qw   = w * 16;

    // stage Q tile (stays for whole kernel)
#pragma unroll
    for (int r = 0; r < 4; r++) {
        int ui = t + 256 * r;
        int d2 = ui >> 5;
        int c4 = (ui & 31) << 2;
        size_t src = ((size_t)bh * 32 + d2) * SEQ + q0g + c4;
        *(uint4*)&QH[d2 * 136 + c4] = *(const uint4*)&qh[src];
        *(uint4*)&QL[d2 * 136 + c4] = *(const uint4*)&ql[src];
    }

    float oacc[8][4];
#pragma unroll
    for (int j = 0; j < 8; j++)
#pragma unroll
        for (int e = 0; e < 4; e++) oacc[j][e] = 0.f;
    float m0 = -1e30f, m1 = -1e30f, l0 = 0.f, l1 = 0.f;

    for (int k0 = 0; k0 < SEQ; k0 += 128) {
        __syncthreads();   // previous chunk consumers done (also covers Q stage)
#pragma unroll
        for (int r = 0; r < 4; r++) {
            int ui = t + 256 * r;
            int d2 = ui >> 5;
            int c4 = (ui & 31) << 2;
            size_t src = ((size_t)bh * 32 + d2) * SEQ + k0 + c4;
            *(uint4*)&KH[d2 * 136 + c4] = *(const uint4*)&kh[src];
            *(uint4*)&KL[d2 * 136 + c4] = *(const uint4*)&kl[src];
        }
#pragma unroll
        for (int r = 0; r < 4; r++) {
            int ui = t + 256 * r;
            int kp = ui >> 4;
            int c4 = (ui & 15) << 2;
            size_t src = ((size_t)bh * 1024 + (k0 >> 1) + kp) * 64 + c4;
            *(uint4*)&VH[kp * 72 + c4] = *(const uint4*)&vh[src];
            *(uint4*)&VL[kp * 72 + c4] = *(const uint4*)&vl[src];
        }
        __syncthreads();

        // ---- S = Q @ K^T (16 x 128 per warp) ----
        float sacc[16][4];
#pragma unroll
        for (int j = 0; j < 16; j++)
#pragma unroll
            for (int e = 0; e < 4; e++) sacc[j][e] = 0.f;

#pragma unroll
        for (int kb = 0; kb < 4; kb++) {
            const int ra = (8 * kb + c) * 136;
            const int rb = ra + 4 * 136;
            uint32_t ah[4], al[4];
            ah[0] = QH[ra + qw + g]; ah[1] = QH[ra + qw + g + 8];
            ah[2] = QH[rb + qw + g]; ah[3] = QH[rb + qw + g + 8];
            al[0] = QL[ra + qw + g]; al[1] = QL[ra + qw + g + 8];
            al[2] = QL[rb + qw + g]; al[3] = QL[rb + qw + g + 8];
#pragma unroll
            for (int j = 0; j < 16; j++) {
                uint32_t b0h = KH[ra + 8 * j + g], b1h = KH[rb + 8 * j + g];
                uint32_t b0l = KL[ra + 8 * j + g], b1l = KL[rb + 8 * j + g];
                mma_bf16(sacc[j], al, b0h, b1h);
                mma_bf16(sacc[j], ah, b0l, b1l);
                mma_bf16(sacc[j], ah, b0h, b1h);
            }
        }

        // ---- online softmax (rows g and g+8 of this warp's 16) ----
        float cm0 = m0, cm1 = m1;
#pragma unroll
        for (int j = 0; j < 16; j++) {
            sacc[j][0] *= 0.125f; sacc[j][1] *= 0.125f;
            sacc[j][2] *= 0.125f; sacc[j][3] *= 0.125f;
            cm0 = fmaxf(cm0, fmaxf(sacc[j][0], sacc[j][1]));
            cm1 = fmaxf(cm1, fmaxf(sacc[j][2], sacc[j][3]));
        }
        cm0 = fmaxf(cm0, __shfl_xor_sync(0xffffffffu, cm0, 1));
        cm0 = fmaxf(cm0, __shfl_xor_sync(0xffffffffu, cm0, 2));
        cm1 = fmaxf(cm1, __shfl_xor_sync(0xffffffffu, cm1, 1));
        cm1 = fmaxf(cm1, __shfl_xor_sync(0xffffffffu, cm1, 2));

        float corr0 = __expf(m0 - cm0);
        float corr1 = __expf(m1 - cm1);
        m0 = cm0; m1 = cm1;
        l0 *= corr0; l1 *= corr1;
#pragma unroll
        for (int j = 0; j < 8; j++) {
            oacc[j][0] *= corr0; oacc[j][1] *= corr0;
            oacc[j][2] *= corr1; oacc[j][3] *= corr1;
        }
        float rs0 = 0.f, rs1 = 0.f;
#pragma unroll
        for (int j = 0; j < 16; j++) {
            float p0 = __expf(sacc[j][0] - m0);
            float p1 = __expf(sacc[j][1] - m0);
            float p2 = __expf(sacc[j][2] - m1);
            float p3 = __expf(sacc[j][3] - m1);
            sacc[j][0] = p0; sacc[j][1] = p1; sacc[j][2] = p2; sacc[j][3] = p3;
            rs0 += p0 + p1; rs1 += p2 + p3;
        }
        rs0 += __shfl_xor_sync(0xffffffffu, rs0, 1);
        rs0 += __shfl_xor_sync(0xffffffffu, rs0, 2);
        rs1 += __shfl_xor_sync(0xffffffffu, rs1, 1);
        rs1 += __shfl_xor_sync(0xffffffffu, rs1, 2);
        l0 += rs0; l1 += rs1;

        // ---- O += P @ V (P in regs: C-frag -> A-frag remap) ----
#pragma unroll
        for (int kb = 0; kb < 8; kb++) {
            uint32_t ph[4], pl[4];
            split2(sacc[2 * kb][0],     sacc[2 * kb][1],     ph[0], pl[0]);
            split2(sacc[2 * kb][2],     sacc[2 * kb][3],     ph[1], pl[1]);
            split2(sacc[2 * kb + 1][0], sacc[2 * kb + 1][1], ph[2], pl[2]);
            split2(sacc[2 * kb + 1][2], sacc[2 * kb + 1][3], ph[3], pl[3]);
            const int rv  = (8 * kb + c) * 72;
            const int rv2 = rv + 4 * 72;
#pragma unroll
            for (int jd = 0; jd < 8; jd++) {
                uint32_t b0h = VH[rv + 8 * jd + g], b1h = VH[rv2 + 8 * jd + g];
                uint32_t b0l = VL[rv + 8 * jd + g], b1l = VL[rv2 + 8 * jd + g];
                mma_bf16(oacc[jd], pl, b0h, b1h);
                mma_bf16(oacc[jd], ph, b0l, b1l);
                mma_bf16(oacc[jd], ph, b0h, b1h);
            }
        }
    }

    // ---- write out ----
    float inv0 = 1.f / l0, inv1 = 1.f / l1;
    const int qrow = q0g + qw + g;
    float* base0 = o + ((size_t)(b * SEQ + qrow)) * EMBED + h * DHEAD;
    float* base1 = base0 + (size_t)8 * EMBED;
#pragma unroll
    for (int jd = 0; jd < 8; jd++) {
        const int col = 8 * jd + 2 * c;
        float2 v0; v0.x = oacc[jd][0] * inv0; v0.y = oacc[jd][1] * inv0;
        float2 v1; v1.x = oacc[jd][2] * inv1; v1.y = oacc[jd][3] * inv1;
        *(float2*)(base0 + col) = v0;
        *(float2*)(base1 + col) = v1;
    }
}

// ---------------- driver -----------------------------------------------------
extern "C" void kernel_launch(void* const* d_in, const int* in_sizes, int n_in,
                              void* d_out, int out_size) {
    const float* x      = (const float*)d_in[0];
    const float* ln1_g  = (const float*)d_in[1];
    const float* ln1_b  = (const float*)d_in[2];
    const float* qkv_w  = (const float*)d_in[3];
    const float* qkv_b  = (const float*)d_in[4];
    const float* proj_w = (const float*)d_in[5];
    const float* proj_b = (const float*)d_in[6];
    const float* ln2_g  = (const float*)d_in[7];
    const float* ln2_b  = (const float*)d_in[8];
    const float* fc1_w  = (const float*)d_in[9];
    const float* fc1_b  = (const float*)d_in[10];
    const float* fc2_w  = (const float*)d_in[11];
    const float* fc2_b  = (const float*)d_in[12];
    float* out = (float*)d_out;

    float *p_ln, *p_qkv, *p_att, *p_x1, *p_fc1;
    uint32_t *p_qh, *p_ql, *p_kh, *p_kl, *p_vh, *p_vl;
    cudaGetSymbolAddress((void**)&p_ln,  g_ln);
    cudaGetSymbolAddress((void**)&p_qkv, g_qkv);
    cudaGetSymbolAddress((void**)&p_att, g_att);
    cudaGetSymbolAddress((void**)&p_x1,  g_x1);
    cudaGetSymbolAddress((void**)&p_fc1, g_fc1);
    cudaGetSymbolAddress((void**)&p_qh,  g_qh);
    cudaGetSymbolAddress((void**)&p_ql,  g_ql);
    cudaGetSymbolAddress((void**)&p_kh,  g_kh);
    cudaGetSymbolAddress((void**)&p_kl,  g_kl);
    cudaGetSymbolAddress((void**)&p_vh,  g_vh);
    cudaGetSymbolAddress((void**)&p_vl,  g_vl);

    cudaFuncSetAttribute(attn2_kernel,
                         cudaFuncAttributeMaxDynamicSharedMemorySize, ASM_BYTES);

    // 1) LN1
    ln_kernel<<<M_TOK / 8, 256>>>(x, ln1_g, ln1_b, p_ln);
    // 2) QKV = LN1 @ qkv_w + qkv_b
    bgemm_kernel<1><<<dim3(QKV_W3 / 128, M_TOK / 128), 256>>>(
        p_ln, qkv_w, qkv_b, nullptr, p_qkv, M_TOK, QKV_W3, EMBED);
    // 3) pre-convert to packed bf16 split operands
    pconv_kernel<<<dim3(SEQ / 128, NBH), 256>>>(p_qkv, p_qh, p_ql, p_kh, p_kl, p_vh, p_vl);
    // 4) flash attention
    attn2_kernel<<<dim3(SEQ / 128, NBH), 256, ASM_BYTES>>>(
        p_qh, p_ql, p_kh, p_kl, p_vh, p_vl, p_att);
    // 5) x1 = x + att @ proj_w + proj_b
    bgemm_kernel<2><<<dim3(EMBED / 128, M_TOK / 128), 256>>>(
        p_att, proj_w, proj_b, x, p_x1, M_TOK, EMBED, EMBED);
    // 6) LN2
    ln_kernel<<<M_TOK / 8, 256>>>(p_x1, ln2_g, ln2_b, p_ln);
    // 7) fc1 = gelu(LN2 @ fc1_w + fc1_b)
    bgemm_kernel<3><<<dim3(HIDDEN / 128, M_TOK / 128), 256>>>(
        p_ln, fc1_w, fc1_b, nullptr, p_fc1, M_TOK, HIDDEN, EMBED);
    // 8) out = x1 + fc1 @ fc2_w + fc2_b
    bgemm_kernel<2><<<dim3(EMBED / 128, M_TOK / 128), 256>>>(
        p_fc1, fc2_w, fc2_b, p_x1, out, M_TOK, EMBED, HIDDEN);
}